// round 15
// baseline (speedup 1.0000x reference)
#include <cuda_runtime.h>

#define BATCH 16
#define CIN   512
#define MID   128
#define GRP   4
#define H     56
#define W     56
#define HW    (H*W)
#define MH    7
#define MW    7
#define EPSV  1e-5f

typedef unsigned long long ull;

__device__ __forceinline__ ull fma2(ull a, ull b, ull c) {
    ull d;
    asm("fma.rn.f32x2 %0, %1, %2, %3;" : "=l"(d) : "l"(a), "l"(b), "l"(c));
    return d;
}
__device__ __forceinline__ ull dup2(float v) {
    ull d;
    asm("mov.b64 %0, {%1, %1};" : "=l"(d) : "f"(v));
    return d;
}
__device__ __forceinline__ void unpack2(ull p, float& lo, float& hi) {
    asm("mov.b64 {%0, %1}, %2;" : "=f"(lo), "=f"(hi) : "l"(p));
}

// Scratch (device globals, no alloc).
__device__ float g_y1[BATCH * MID * HW];   // relu(bn1(conv1(x*m))) * m
// Pre-transposed weights:
__device__ float tw1[4 * 128 * 32];        // [g][ic][oc]
__device__ float tw2[4 * 32 * 9 * 32];     // [g][ic][tap][oc]
__device__ float tw3[4 * 32 * 128];        // [g][ic][oc]

__global__ void setup_tw(const float* __restrict__ w1,
                         const float* __restrict__ w2,
                         const float* __restrict__ w3)
{
    int i = blockIdx.x * 256 + threadIdx.x;
    if (i < 16384) {                       // tw1[g][ic][oc32]
        int g = i >> 12, r = i & 4095, ic = r >> 5, oc = r & 31;
        tw1[i] = w1[(g * 32 + oc) * 128 + ic];
    }
    if (i < 36864) {                       // tw2[g][ic][kk][oc32]
        int g = i / 9216, r = i % 9216, ic = r / 288, r2 = r % 288;
        int kk = r2 >> 5, oc = r2 & 31;
        tw2[i] = w2[(g * 32 + oc) * 288 + ic * 9 + kk];
    }
    if (i < 16384) {                       // tw3[g][ic][oc128]
        int g = i >> 12, r = i & 4095, ic = r >> 7, oc = r & 127;
        tw3[i] = w3[(g * 128 + oc) * 32 + ic];
    }
}

// ---------------------------------------------------------------------------
// Kernel 1: 1x1 grouped conv (512->128) + BN + ReLU (+mask), 8x8 tile.
// (unchanged from R12 — measured component)
// ---------------------------------------------------------------------------
__global__ __launch_bounds__(256, 3) void k1_conv1(
    const float* __restrict__ x, const float* __restrict__ mask,
    const float* __restrict__ g1, const float* __restrict__ b1,
    const float* __restrict__ m1, const float* __restrict__ v1)
{
    const int bh = blockIdx.x / 7, bw = blockIdx.x % 7;
    const int gp = blockIdx.y, b = blockIdx.z;      // group pair (0/1)
    const int h0 = bh * 8, w0 = bw * 8;
    const int t = threadIdx.x;
    const int ocq = t >> 4;
    const int pxq = t & 15;
    const int r = pxq >> 1, cst = (pxq & 1) * 4;

    const float m0 = mask[((b * GRP + gp * 2 + 0) * MH + bh) * MW + bw];
    const float m1v = mask[((b * GRP + gp * 2 + 1) * MH + bh) * MW + bw];

    if (m0 == 0.0f && m1v == 0.0f) {
        const float4 z = make_float4(0.f, 0.f, 0.f, 0.f);
        #pragma unroll
        for (int k = 0; k < 4; k++) {
            int gc = gp * 64 + ocq * 4 + k;
            *(float4*)&g_y1[((b * MID + gc) * H + h0 + r) * W + w0 + cst] = z;
        }
        return;
    }

    __shared__ float  w_s[128][68];
    __shared__ float4 x_s[2][32][16];
    float4* xlin = &x_s[0][0][0];

    {
        const float4* src = (const float4*)(tw1 + gp * 2 * 4096);
        float4* dst = (float4*)&w_s[0][0];
        #pragma unroll
        for (int j = 0; j < 8; j++) {
            int i = t + j * 256;
            int gg = i >> 10, rem = i & 1023;
            int ic = rem >> 3, oc4 = rem & 7;
            dst[ic * 17 + gg * 8 + oc4] = src[i];
        }
    }

    const int myg = ocq >> 3;
    const bool active = (myg ? m1v : m0) != 0.0f;

    const float* xbase = x + (long)(b * CIN + gp * 2 * 128) * HW;
    long off[4];
    unsigned lmask = 0;
    #pragma unroll
    for (int j = 0; j < 4; j++) {
        int id = t + j * 256;
        int gg = id >> 9, ic = (id >> 4) & 31, p4 = id & 15;
        int rr = p4 >> 1, c2 = (p4 & 1) * 4;
        off[j] = ((long)(gg * 128 + ic) * H + h0 + rr) * W + w0 + c2;
        if ((gg ? m1v : m0) != 0.0f) lmask |= (1u << j);
    }

    #pragma unroll
    for (int j = 0; j < 4; j++) {
        float4 v = make_float4(0.f, 0.f, 0.f, 0.f);
        if (lmask & (1u << j)) v = *(const float4*)(xbase + off[j]);
        xlin[t + j * 256] = v;
    }
    __syncthreads();

    ull acc[4][2];
    #pragma unroll
    for (int k = 0; k < 4; k++) { acc[k][0] = 0ull; acc[k][1] = 0ull; }

    for (int cc = 0; cc < 4; cc++) {
        float4 pre[4];
        if (cc < 3) {
            #pragma unroll
            for (int j = 0; j < 4; j++) {
                pre[j] = make_float4(0.f, 0.f, 0.f, 0.f);
                if (lmask & (1u << j))
                    pre[j] = *(const float4*)(xbase + off[j] + (long)(cc + 1) * 32 * HW);
            }
        }
        if (active) {
            #pragma unroll
            for (int icc = 0; icc < 32; icc++) {
                ulonglong2 xp = *(const ulonglong2*)&x_s[cc & 1 ? myg : myg][icc][pxq];
                // NOTE: single logical buffer indexed by myg; see store below
                float4 wv = *(const float4*)&w_s[cc * 32 + icc][ocq * 4];
                ull wd;
                wd = dup2(wv.x); acc[0][0] = fma2(wd, xp.x, acc[0][0]); acc[0][1] = fma2(wd, xp.y, acc[0][1]);
                wd = dup2(wv.y); acc[1][0] = fma2(wd, xp.x, acc[1][0]); acc[1][1] = fma2(wd, xp.y, acc[1][1]);
                wd = dup2(wv.z); acc[2][0] = fma2(wd, xp.x, acc[2][0]); acc[2][1] = fma2(wd, xp.y, acc[2][1]);
                wd = dup2(wv.w); acc[3][0] = fma2(wd, xp.x, acc[3][0]); acc[3][1] = fma2(wd, xp.y, acc[3][1]);
            }
        }
        if (cc < 3) {
            __syncthreads();
            #pragma unroll
            for (int j = 0; j < 4; j++)
                xlin[t + j * 256] = pre[j];
            __syncthreads();
        }
    }

    const float mymask = myg ? m1v : m0;
    #pragma unroll
    for (int k = 0; k < 4; k++) {
        int gc = gp * 64 + ocq * 4 + k;
        float sc = g1[gc] * rsqrtf(v1[gc] + EPSV);
        float bi = b1[gc] - m1[gc] * sc;
        float4 v = make_float4(0.f, 0.f, 0.f, 0.f);
        if (mymask != 0.0f) {
            float a0, a1, a2, a3;
            unpack2(acc[k][0], a0, a1);
            unpack2(acc[k][1], a2, a3);
            v.x = fmaxf(a0 * sc + bi, 0.0f);
            v.y = fmaxf(a1 * sc + bi, 0.0f);
            v.z = fmaxf(a2 * sc + bi, 0.0f);
            v.w = fmaxf(a3 * sc + bi, 0.0f);
        }
        *(float4*)&g_y1[((b * MID + gc) * H + h0 + r) * W + w0 + cst] = v;
    }
}

// ---------------------------------------------------------------------------
// Persistent fused Kernel 2+3. Grid (74, GRP): CTA pinned to group g,
// loops over items idx = cid, cid+74, ... < 784 where b = idx & 15,
// tile = idx >> 4. Weights (w2 full + w3) loaded ONCE per CTA. Halo for
// item i+1 prefetched to registers during conv2(i), double-buffered smem.
// 2 barriers per item. 92 KB smem -> 2 CTA/SM = 296 CTAs = 1 wave.
// smem (floats): W2 [0,9216)  [ic32][tap9][oc32]
//                W3 [9216,13312) [ic32][oc128]
//                H0 [13312,17152) halo buf0 [32][120 pad12]
//                H1 [17152,20992) halo buf1
//                Y2 [20992,23040) y2 [32 oc][64 px]
// ---------------------------------------------------------------------------
#define P_W2 0
#define P_W3 9216
#define P_H0 13312
#define P_H1 17152
#define P_Y2 20992
#define P_SMEM (23040 * 4)
#define NITEMS 784
#define NCTA   74

__global__ __launch_bounds__(256, 2) void k23_persist(
    const float* __restrict__ x, const float* __restrict__ mask,
    const float* __restrict__ g2, const float* __restrict__ b2,
    const float* __restrict__ m2, const float* __restrict__ v2,
    const float* __restrict__ g3, const float* __restrict__ b3,
    const float* __restrict__ m3, const float* __restrict__ v3,
    float* __restrict__ out)
{
    const int cid = blockIdx.x;             // 0..73
    const int g = blockIdx.y;
    const int t = threadIdx.x;
    const int pxq = t & 15;                 // 4-px quad
    const int ocq2 = t >> 4;                // conv2: 2 oc ; conv3: 8 oc
    const int r = pxq >> 1, cst = (pxq & 1) * 4;

    extern __shared__ float sm[];

    // BN constants (per-channel, item-independent)
    float sc2[2], bi2[2];
    #pragma unroll
    for (int k = 0; k < 2; k++) {
        int gc = g * 32 + ocq2 * 2 + k;
        sc2[k] = g2[gc] * rsqrtf(v2[gc] + EPSV);
        bi2[k] = b2[gc] - m2[gc] * sc2[k];
    }
    float sc3[8], bi3[8];
    #pragma unroll
    for (int k = 0; k < 8; k++) {
        int gc = g * 128 + ocq2 * 8 + k;
        sc3[k] = g3[gc] * rsqrtf(v3[gc] + EPSV);
        bi3[k] = b3[gc] - m3[gc] * sc3[k];
    }

    // Weights once
    {
        const float4* s2 = (const float4*)(tw2 + g * 9216);
        float4* d2 = (float4*)(sm + P_W2);
        #pragma unroll
        for (int j = 0; j < 9; j++) {
            int i = t + j * 256;
            if (i < 2304) d2[i] = s2[i];
        }
        const float4* s3 = (const float4*)(tw3 + g * 4096);
        float4* d3 = (float4*)(sm + P_W3);
        #pragma unroll
        for (int j = 0; j < 4; j++)
            d3[t + j * 256] = s3[t + j * 256];
    }

    // Prologue: halo for first item into H0
    int cur = cid;
    float curm = 0.0f;
    if (cur < NITEMS) {
        int b = cur & 15, tile = cur >> 4;
        int bh = tile / 7, bw = tile % 7;
        curm = mask[((b * GRP + g) * MH + bh) * MW + bw];
        if (curm != 0.0f) {
            const float* src = g_y1 + (long)(b * MID + g * 32) * HW;
            int h0 = bh * 8, w0 = bw * 8;
            #pragma unroll
            for (int j = 0; j < 13; j++) {
                int i = t + j * 256;
                if (i < 3200) {
                    int ic = i / 100, p = i % 100, pr = p / 10, pc = p % 10;
                    int rr = h0 + pr - 1, cc = w0 + pc - 1;
                    float v = 0.0f;
                    if (rr >= 0 && rr < H && cc >= 0 && cc < W)
                        v = src[ic * HW + rr * W + cc];
                    sm[P_H0 + ic * 120 + pr * 12 + pc] = v;
                }
            }
        }
    }
    __syncthreads();

    int buf = 0;
    for (; cur < NITEMS; cur += NCTA, buf ^= 1) {
        const int b = cur & 15, tile = cur >> 4;
        const int bh = tile / 7, bw = tile % 7;
        const int h0 = bh * 8, w0 = bw * 8;

        // prefetch next item's halo into registers
        const int nxt = cur + NCTA;
        float nxtm = 0.0f;
        float pre[13];
        if (nxt < NITEMS) {
            int nb = nxt & 15, ntile = nxt >> 4;
            int nbh = ntile / 7, nbw = ntile % 7;
            nxtm = mask[((nb * GRP + g) * MH + nbh) * MW + nbw];
            if (nxtm != 0.0f) {
                const float* src = g_y1 + (long)(nb * MID + g * 32) * HW;
                int nh0 = nbh * 8, nw0 = nbw * 8;
                #pragma unroll
                for (int j = 0; j < 13; j++) {
                    int i = t + j * 256;
                    float v = 0.0f;
                    if (i < 3200) {
                        int ic = i / 100, p = i % 100, pr = p / 10, pc = p % 10;
                        int rr = nh0 + pr - 1, cc = nw0 + pc - 1;
                        if (rr >= 0 && rr < H && cc >= 0 && cc < W)
                            v = src[ic * HW + rr * W + cc];
                    }
                    pre[j] = v;
                }
            }
        }

        if (curm != 0.0f) {
            // ---- conv2 ----
            const float* hb0 = sm + (buf ? P_H1 : P_H0);
            ull acc2p[4] = {0ull, 0ull, 0ull, 0ull};   // [px], oc-pair packed
            #pragma unroll 4
            for (int ic = 0; ic < 32; ic++) {
                const float* hb = hb0 + ic * 120;
                const float* wb = sm + P_W2 + ic * 288;
                #pragma unroll
                for (int kr = 0; kr < 3; kr++) {
                    float4 a = *(const float4*)&hb[(r + kr) * 12 + cst];
                    float2 bq = *(const float2*)&hb[(r + kr) * 12 + cst + 4];
                    ull xd[6];
                    xd[0] = dup2(a.x); xd[1] = dup2(a.y); xd[2] = dup2(a.z);
                    xd[3] = dup2(a.w); xd[4] = dup2(bq.x); xd[5] = dup2(bq.y);
                    #pragma unroll
                    for (int kc = 0; kc < 3; kc++) {
                        ull wv = *(const ull*)&wb[(kr * 3 + kc) * 32 + ocq2 * 2];
                        acc2p[0] = fma2(wv, xd[kc + 0], acc2p[0]);
                        acc2p[1] = fma2(wv, xd[kc + 1], acc2p[1]);
                        acc2p[2] = fma2(wv, xd[kc + 2], acc2p[2]);
                        acc2p[3] = fma2(wv, xd[kc + 3], acc2p[3]);
                    }
                }
            }
            // bn2 + relu -> Y2
            float e0[4], e1[4];
            #pragma unroll
            for (int q = 0; q < 4; q++) unpack2(acc2p[q], e0[q], e1[q]);
            #pragma unroll
            for (int k = 0; k < 2; k++) {
                const float* av = k ? e1 : e0;
                float4 v;
                v.x = fmaxf(av[0] * sc2[k] + bi2[k], 0.0f);
                v.y = fmaxf(av[1] * sc2[k] + bi2[k], 0.0f);
                v.z = fmaxf(av[2] * sc2[k] + bi2[k], 0.0f);
                v.w = fmaxf(av[3] * sc2[k] + bi2[k], 0.0f);
                *(float4*)&sm[P_Y2 + (ocq2 * 2 + k) * 64 + pxq * 4] = v;
            }
        } else {
            // masked: out = relu(bias3 + x)
            #pragma unroll
            for (int k = 0; k < 8; k++) {
                int gc = g * 128 + ocq2 * 8 + k;
                long idx = ((long)(b * CIN + gc) * H + h0 + r) * W + w0 + cst;
                float4 xv = *(const float4*)&x[idx];
                float4 v;
                v.x = fmaxf(bi3[k] + xv.x, 0.0f);
                v.y = fmaxf(bi3[k] + xv.y, 0.0f);
                v.z = fmaxf(bi3[k] + xv.z, 0.0f);
                v.w = fmaxf(bi3[k] + xv.w, 0.0f);
                *(float4*)&out[idx] = v;
            }
        }

        // store prefetched halo into the other buffer
        if (nxt < NITEMS && nxtm != 0.0f) {
            float* dstb = sm + (buf ? P_H0 : P_H1);
            #pragma unroll
            for (int j = 0; j < 13; j++) {
                int i = t + j * 256;
                if (i < 3200) {
                    int ic = i / 100, p = i % 100, pr = p / 10, pc = p % 10;
                    dstb[ic * 120 + pr * 12 + pc] = pre[j];
                }
            }
        }
        __syncthreads();    // B1: Y2 + halo(nxt) visible

        if (curm != 0.0f) {
            // ---- conv3 + residual ----
            const float* w3s = sm + P_W3;
            ull acc3p[4][4];
            #pragma unroll
            for (int p = 0; p < 4; p++)
                #pragma unroll
                for (int q = 0; q < 4; q++) acc3p[p][q] = 0ull;

            #pragma unroll 4
            for (int ic = 0; ic < 32; ic++) {
                float4 xv = *(const float4*)&sm[P_Y2 + ic * 64 + pxq * 4];
                ull xd0 = dup2(xv.x), xd1 = dup2(xv.y), xd2 = dup2(xv.z), xd3 = dup2(xv.w);
                const float* wr = &w3s[ic * 128 + ocq2 * 8];
                ulonglong2 wa = *(const ulonglong2*)wr;
                ulonglong2 wb2 = *(const ulonglong2*)(wr + 4);
                acc3p[0][0] = fma2(wa.x, xd0, acc3p[0][0]);
                acc3p[0][1] = fma2(wa.x, xd1, acc3p[0][1]);
                acc3p[0][2] = fma2(wa.x, xd2, acc3p[0][2]);
                acc3p[0][3] = fma2(wa.x, xd3, acc3p[0][3]);
                acc3p[1][0] = fma2(wa.y, xd0, acc3p[1][0]);
                acc3p[1][1] = fma2(wa.y, xd1, acc3p[1][1]);
                acc3p[1][2] = fma2(wa.y, xd2, acc3p[1][2]);
                acc3p[1][3] = fma2(wa.y, xd3, acc3p[1][3]);
                acc3p[2][0] = fma2(wb2.x, xd0, acc3p[2][0]);
                acc3p[2][1] = fma2(wb2.x, xd1, acc3p[2][1]);
                acc3p[2][2] = fma2(wb2.x, xd2, acc3p[2][2]);
                acc3p[2][3] = fma2(wb2.x, xd3, acc3p[2][3]);
                acc3p[3][0] = fma2(wb2.y, xd0, acc3p[3][0]);
                acc3p[3][1] = fma2(wb2.y, xd1, acc3p[3][1]);
                acc3p[3][2] = fma2(wb2.y, xd2, acc3p[3][2]);
                acc3p[3][3] = fma2(wb2.y, xd3, acc3p[3][3]);
            }

            #pragma unroll
            for (int p = 0; p < 4; p++) {
                float e[2][4];
                #pragma unroll
                for (int q = 0; q < 4; q++) unpack2(acc3p[p][q], e[0][q], e[1][q]);
                #pragma unroll
                for (int k = 0; k < 2; k++) {
                    int kk = p * 2 + k;
                    int gc = g * 128 + ocq2 * 8 + kk;
                    long idx = ((long)(b * CIN + gc) * H + h0 + r) * W + w0 + cst;
                    float4 xv = *(const float4*)&x[idx];
                    float4 v;
                    v.x = fmaxf(e[k][0] * sc3[kk] + bi3[kk] + xv.x, 0.0f);
                    v.y = fmaxf(e[k][1] * sc3[kk] + bi3[kk] + xv.y, 0.0f);
                    v.z = fmaxf(e[k][2] * sc3[kk] + bi3[kk] + xv.z, 0.0f);
                    v.w = fmaxf(e[k][3] * sc3[kk] + bi3[kk] + xv.w, 0.0f);
                    *(float4*)&out[idx] = v;
                }
            }
        }

        curm = nxtm;
        __syncthreads();    // B2: Y2 reads done before next item's writes
    }
}

// ---------------------------------------------------------------------------
extern "C" void kernel_launch(void* const* d_in, const int* in_sizes, int n_in,
                              void* d_out, int out_size)
{
    const float* x    = (const float*)d_in[0];
    const float* mask = (const float*)d_in[1];
    const float* w1   = (const float*)d_in[2];
    const float* g1   = (const float*)d_in[3];
    const float* b1   = (const float*)d_in[4];
    const float* m1   = (const float*)d_in[5];
    const float* v1   = (const float*)d_in[6];
    const float* w2   = (const float*)d_in[7];
    const float* g2   = (const float*)d_in[8];
    const float* b2   = (const float*)d_in[9];
    const float* m2   = (const float*)d_in[10];
    const float* v2   = (const float*)d_in[11];
    const float* w3   = (const float*)d_in[12];
    const float* g3   = (const float*)d_in[13];
    const float* b3   = (const float*)d_in[14];
    const float* m3   = (const float*)d_in[15];
    const float* v3   = (const float*)d_in[16];
    float* out = (float*)d_out;

    cudaFuncSetAttribute(k23_persist, cudaFuncAttributeMaxDynamicSharedMemorySize, P_SMEM);

    setup_tw<<<144, 256>>>(w1, w2, w3);
    dim3 grid1(49, 2, BATCH);
    k1_conv1<<<grid1, 256>>>(x, mask, g1, b1, m1, v1);
    dim3 grid2(NCTA, GRP);
    k23_persist<<<grid2, 256, P_SMEM>>>(x, mask, g2, b2, m2, v2,
                                        g3, b3, m3, v3, out);
}